// round 2
// baseline (speedup 1.0000x reference)
#include <cuda_runtime.h>
#include <cuda_bf16.h>

// Problem constants: pred [8,16,512,512] f32, target [8,512,512] int32
#define N_IMG   8
#define N_CLS   16
#define HW      262144            // 512*512
#define NPIX    (N_IMG * HW)      // 2097152
#define CHW     (N_CLS * HW)
#define HW4     (HW / 4)          // 65536 float4 groups per channel-plane
#define BPI     128               // blocks per image in main kernel
#define MAIN_BLOCKS (N_IMG * BPI) // 1024
#define HIST_BLOCKS 1024          // 1024*256 threads, 2 int4 each = NPIX/4*2

// Scratch (no cudaMalloc allowed)
__device__ unsigned int g_counts[N_CLS];
__device__ float        g_num[N_IMG];
__device__ float        g_den[N_IMG];

// ---------------------------------------------------------------------------
// Kernel 0: zero scratch
// ---------------------------------------------------------------------------
__global__ void dwce_zero() {
    int t = threadIdx.x;
    if (t < N_CLS) g_counts[t] = 0u;
    if (t < N_IMG) { g_num[t] = 0.0f; g_den[t] = 0.0f; }
}

// ---------------------------------------------------------------------------
// Kernel 1: per-class histogram of int32 targets using nibble-packed
// register counters (8 increments per thread, capacity 15 per nibble).
// Warp reduce -> shared -> one global atomic per class per block.
// ---------------------------------------------------------------------------
__global__ __launch_bounds__(256) void dwce_hist(const int* __restrict__ target) {
    __shared__ unsigned int sh[N_CLS];
    int tid = threadIdx.x;
    if (tid < N_CLS) sh[tid] = 0u;
    __syncthreads();

    const int4* tv = (const int4*)target;       // NPIX/4 = 524288 int4 groups
    int base = blockIdx.x * 256 + tid;          // [0, 262144)
    unsigned long long cnt = 0ull;
#pragma unroll
    for (int k = 0; k < 2; k++) {
        int4 a = tv[base + k * 262144];
        cnt += (1ull << (a.x * 4)) + (1ull << (a.y * 4))
             + (1ull << (a.z * 4)) + (1ull << (a.w * 4));
    }

#pragma unroll
    for (int c = 0; c < N_CLS; c++) {
        unsigned int v = (unsigned int)((cnt >> (4 * c)) & 0xFull);
        v = __reduce_add_sync(0xFFFFFFFFu, v);
        if ((tid & 31) == 0 && v) atomicAdd(&sh[c], v);
    }
    __syncthreads();
    if (tid < N_CLS && sh[tid]) atomicAdd(&g_counts[tid], sh[tid]);
}

// ---------------------------------------------------------------------------
// Kernel 2: main pass. Each thread handles 2 groups of 4 consecutive pixels.
// Per group: 1 int4 target load + 16 float4 channel loads (coalesced),
// softmax-lse, gather at target via unrolled compare-select, weighted
// accumulate. Block reduce -> one float atomicAdd pair per block.
// ---------------------------------------------------------------------------
__global__ __launch_bounds__(256, 2) void dwce_main(const float* __restrict__ pred,
                                                    const int* __restrict__ target) {
    __shared__ float sh_w[N_CLS];
    __shared__ float sn[8], sd[8];
    int tid = threadIdx.x;
    if (tid < N_CLS) {
        unsigned int c = g_counts[tid];
        sh_w[tid] = c ? (1.0f / (16.0f * (float)c)) : 0.0f;
    }
    __syncthreads();

    int img = blockIdx.x >> 7;      // / BPI
    int blk = blockIdx.x & (BPI - 1);
    const float4* pv = (const float4*)(pred + (size_t)img * CHW);
    const int4*   tv = (const int4*)(target + (size_t)img * HW);

    float num = 0.0f, den = 0.0f;

#pragma unroll
    for (int k = 0; k < 2; k++) {
        int g = k * 32768 + blk * 256 + tid;    // float4-group index within image
        int4 t4 = tv[g];
        int t0 = t4.x, t1 = t4.y, t2 = t4.z, t3 = t4.w;

        float4 v[N_CLS];
#pragma unroll
        for (int c = 0; c < N_CLS; c++) v[c] = pv[c * HW4 + g];

        // max over channels
        float4 m = v[0];
#pragma unroll
        for (int c = 1; c < N_CLS; c++) {
            m.x = fmaxf(m.x, v[c].x); m.y = fmaxf(m.y, v[c].y);
            m.z = fmaxf(m.z, v[c].z); m.w = fmaxf(m.w, v[c].w);
        }

        // gather pred[target] (compare-select, no dynamic reg index) + exp-sum
        float vt0 = 0.0f, vt1 = 0.0f, vt2 = 0.0f, vt3 = 0.0f;
        float4 s = make_float4(0.0f, 0.0f, 0.0f, 0.0f);
#pragma unroll
        for (int c = 0; c < N_CLS; c++) {
            if (c == t0) vt0 = v[c].x;
            if (c == t1) vt1 = v[c].y;
            if (c == t2) vt2 = v[c].z;
            if (c == t3) vt3 = v[c].w;
            s.x += __expf(v[c].x - m.x);
            s.y += __expf(v[c].y - m.y);
            s.z += __expf(v[c].z - m.z);
            s.w += __expf(v[c].w - m.w);
        }

        float l0 = m.x + __logf(s.x);
        float l1 = m.y + __logf(s.y);
        float l2 = m.z + __logf(s.z);
        float l3 = m.w + __logf(s.w);

        float w0 = sh_w[t0], w1 = sh_w[t1], w2 = sh_w[t2], w3 = sh_w[t3];
        num += w0 * (vt0 - l0);
        num += w1 * (vt1 - l1);
        num += w2 * (vt2 - l2);
        num += w3 * (vt3 - l3);
        den += (w0 + w1) + (w2 + w3);
    }

    // warp reduce
#pragma unroll
    for (int o = 16; o > 0; o >>= 1) {
        num += __shfl_down_sync(0xFFFFFFFFu, num, o);
        den += __shfl_down_sync(0xFFFFFFFFu, den, o);
    }
    int w = tid >> 5, lane = tid & 31;
    if (lane == 0) { sn[w] = num; sd[w] = den; }
    __syncthreads();
    if (tid == 0) {
        float a = 0.0f, b = 0.0f;
#pragma unroll
        for (int i = 0; i < 8; i++) { a += sn[i]; b += sd[i]; }
        atomicAdd(&g_num[img], a);
        atomicAdd(&g_den[img], b);
    }
}

// ---------------------------------------------------------------------------
// Kernel 3: finalize  loss = -(mean over images of num/den)
// ---------------------------------------------------------------------------
__global__ void dwce_final(float* __restrict__ out) {
    if (threadIdx.x == 0) {
        float acc = 0.0f;
#pragma unroll
        for (int i = 0; i < N_IMG; i++) acc += g_num[i] / g_den[i];
        out[0] = -acc * (1.0f / (float)N_IMG);
    }
}

// ---------------------------------------------------------------------------
extern "C" void kernel_launch(void* const* d_in, const int* in_sizes, int n_in,
                              void* d_out, int out_size) {
    const float* pred   = (const float*)d_in[0];
    const int*   target = (const int*)d_in[1];
    // d_in[2] (weights) is ignored by the reference module.
    float* out = (float*)d_out;

    dwce_zero<<<1, 32>>>();
    dwce_hist<<<HIST_BLOCKS, 256>>>(target);
    dwce_main<<<MAIN_BLOCKS, 256>>>(pred, target);
    dwce_final<<<1, 32>>>(out);
}